// round 10
// baseline (speedup 1.0000x reference)
#include <cuda_runtime.h>
#include <cuda_fp16.h>
#include <math.h>

// Shapes: x[2,2048,1024] f32 -> T=4096, E=1024; Wr[1024,8]; W1[8,1024,4096];
// b1[8,4096]; W2[8,4096,1024]; b2[8,1024]; top_k=2.
#define TNUM 4096
#define EDIM 1024
#define NEXP 8
#define HDIM 4096
#define CAP  4096

// Device-global scratch. NEVER pass these as kernel args from host code.
__device__ __half g_xh [(size_t)TNUM * EDIM];
__device__ __half g_w1t[(size_t)NEXP * HDIM * EDIM];     // [e][n=H][k=E]
__device__ __half g_w2t[(size_t)NEXP * EDIM * HDIM];     // [e][n=E][k=H]
__device__ __half g_hid[(size_t)NEXP * CAP * HDIM];
__device__ int    g_cnt[NEXP];
__device__ int    g_tok[NEXP * CAP];
__device__ float  g_wgt[NEXP * CAP];

__device__ __forceinline__ float gelu_exact(float v) {
    return 0.5f * v * (1.0f + erff(v * 0.70710678118654752f));
}

__device__ __forceinline__ void mma_f16(float* c, const unsigned* a, const unsigned* b) {
    asm volatile(
        "mma.sync.aligned.m16n8k16.row.col.f32.f16.f16.f32 "
        "{%0,%1,%2,%3}, {%4,%5,%6,%7}, {%8,%9}, {%0,%1,%2,%3};"
        : "+f"(c[0]), "+f"(c[1]), "+f"(c[2]), "+f"(c[3])
        : "r"(a[0]), "r"(a[1]), "r"(a[2]), "r"(a[3]), "r"(b[0]), "r"(b[1]));
}

__device__ __forceinline__ void ldsm_x4(unsigned* d, unsigned addr) {
    asm volatile("ldmatrix.sync.aligned.m8n8.x4.shared.b16 {%0,%1,%2,%3}, [%4];"
                 : "=r"(d[0]), "=r"(d[1]), "=r"(d[2]), "=r"(d[3]) : "r"(addr));
}

__device__ __forceinline__ void cp16(void* smem, const void* gmem, int src_bytes) {
    unsigned s = (unsigned)__cvta_generic_to_shared(smem);
    asm volatile("cp.async.cg.shared.global [%0], [%1], 16, %2;\n"
                 :: "r"(s), "l"(gmem), "r"(src_bytes));
}
__device__ __forceinline__ void cp_commit() { asm volatile("cp.async.commit_group;\n"); }
__device__ __forceinline__ void cp_wait1()  { asm volatile("cp.async.wait_group 1;\n"); }

// ---------------------------------------------------------------------------
// K0: zero output + counters
// ---------------------------------------------------------------------------
__global__ void k_zero(float* __restrict__ out) {
    size_t i = (size_t)blockIdx.x * blockDim.x + threadIdx.x;
    size_t n4 = (size_t)TNUM * EDIM / 4;
    if (i < n4) ((float4*)out)[i] = make_float4(0.f, 0.f, 0.f, 0.f);
    if (blockIdx.x == 0 && threadIdx.x < NEXP) g_cnt[threadIdx.x] = 0;
}

// Kc: x f32 -> f16
__global__ void k_convx(const float* __restrict__ x) {
    size_t i = (size_t)blockIdx.x * blockDim.x + threadIdx.x;
    if (i < (size_t)TNUM * EDIM / 2) {
        float2 v = ((const float2*)x)[i];
        ((half2*)g_xh)[i] = __floats2half2_rn(v.x, v.y);
    }
}

// Kw: W [e][K][N] f32 -> WT [e][N][K] f16; destination chosen in device code.
template <int WHICH>  // 0 -> g_w1t (K=EDIM,N=HDIM), 1 -> g_w2t (K=HDIM,N=EDIM)
__global__ __launch_bounds__(256) void k_convW(const float* __restrict__ W) {
    const int K = WHICH ? HDIM : EDIM;
    const int N = WHICH ? EDIM : HDIM;
    __half* WT = WHICH ? g_w2t : g_w1t;

    __shared__ float s[32][33];
    int e = blockIdx.z;
    int k0 = blockIdx.y * 32, n0 = blockIdx.x * 32;
    const float* Wp = W + ((size_t)e * K + k0) * N + n0;
    __half* Tp = WT + ((size_t)e * N + n0) * K + k0;
    int tx = threadIdx.x & 31, ty = threadIdx.x >> 5;
#pragma unroll
    for (int i = 0; i < 32; i += 8)
        s[ty + i][tx] = Wp[(size_t)(ty + i) * N + tx];
    __syncthreads();
#pragma unroll
    for (int i = 0; i < 32; i += 8) {
        int n = ty + i;
        Tp[(size_t)n * K + tx] = __float2half_rn(s[tx][n]);
    }
}

// ---------------------------------------------------------------------------
// K1: router (exact fp32): logits, top-2, 2-way softmax, compact lists
// ---------------------------------------------------------------------------
__global__ __launch_bounds__(256) void k_router(const float* __restrict__ x,
                                                const float* __restrict__ Wr,
                                                const float* __restrict__ br) {
    int warp = (blockIdx.x * blockDim.x + threadIdx.x) >> 5;
    int lane = threadIdx.x & 31;
    if (warp >= TNUM) return;
    const float* xr = x + (size_t)warp * EDIM;

    float acc[NEXP];
#pragma unroll
    for (int n = 0; n < NEXP; n++) acc[n] = 0.f;
    for (int k = lane; k < EDIM; k += 32) {
        float xv = xr[k];
        const float4* w4 = (const float4*)(Wr + (size_t)k * NEXP);
        float4 a = w4[0], b = w4[1];
        acc[0] += xv * a.x; acc[1] += xv * a.y; acc[2] += xv * a.z; acc[3] += xv * a.w;
        acc[4] += xv * b.x; acc[5] += xv * b.y; acc[6] += xv * b.z; acc[7] += xv * b.w;
    }
#pragma unroll
    for (int n = 0; n < NEXP; n++)
#pragma unroll
        for (int o = 16; o > 0; o >>= 1)
            acc[n] += __shfl_xor_sync(0xffffffffu, acc[n], o);
    if (lane == 0) {
        float l[NEXP];
#pragma unroll
        for (int n = 0; n < NEXP; n++) l[n] = acc[n] + br[n];
        int i0 = 0;
#pragma unroll
        for (int n = 1; n < NEXP; n++) if (l[n] > l[i0]) i0 = n;
        int i1 = -1;
#pragma unroll
        for (int n = 0; n < NEXP; n++) {
            if (n == i0) continue;
            if (i1 < 0 || l[n] > l[i1]) i1 = n;
        }
        float d  = __expf(l[i1] - l[i0]);
        float w0 = 1.f / (1.f + d);
        float w1 = d * w0;
        int s0 = atomicAdd(&g_cnt[i0], 1);
        g_tok[i0 * CAP + s0] = warp;  g_wgt[i0 * CAP + s0] = w0;
        int s1 = atomicAdd(&g_cnt[i1], 1);
        g_tok[i1 * CAP + s1] = warp;  g_wgt[i1 * CAP + s1] = w1;
    }
}

// ---------------------------------------------------------------------------
// fp16 grouped GEMMs: 128x128 tile, BK=32, 128 thr = 4 warps (2x2),
// warp tile 64x64, mma m16n8k16, ldmatrix, 3-stage cp.async pipeline.
// Unpadded 64B rows, XOR chunk swizzle pc = c ^ ((r>>1)&3): conflict-free.
// ---------------------------------------------------------------------------
#define BK 32
#define NSTG 3

__device__ __forceinline__ unsigned sw_off(int r, int c) {  // offset in halves
    return (unsigned)(r * BK + ((c ^ ((r >> 1) & 3)) << 3));
}

__device__ __forceinline__ void mma_stage(const __half* As, const __half* Bs,
                                          int wm, int wn, int lane,
                                          float acc[4][8][4]) {
    unsigned abase = (unsigned)__cvta_generic_to_shared(As);
    unsigned bbase = (unsigned)__cvta_generic_to_shared(Bs);
    int arow = lane & 15;
    int brow = ((lane >> 4) << 3) + (lane & 7);
#pragma unroll
    for (int ks = 0; ks < BK; ks += 16) {
        unsigned a[4][4], b[4][4];
        int achunk = (ks >> 3) + (lane >> 4);
        int bchunk = (ks >> 3) + ((lane >> 3) & 1);
#pragma unroll
        for (int mi = 0; mi < 4; mi++)
            ldsm_x4(a[mi], abase + 2u * sw_off(wm + mi * 16 + arow, achunk));
#pragma unroll
        for (int nj2 = 0; nj2 < 4; nj2++)
            ldsm_x4(b[nj2], bbase + 2u * sw_off(wn + nj2 * 16 + brow, bchunk));
#pragma unroll
        for (int mi = 0; mi < 4; mi++)
#pragma unroll
            for (int nj = 0; nj < 8; nj++)
                mma_f16(acc[mi][nj], a[mi], &b[nj >> 1][(nj & 1) * 2]);
    }
}

// K2: hid = gelu(gather(x_h) @ W1T[e]^T + b1[e])
__global__ __launch_bounds__(128, 2) void k_ffn1(const float* __restrict__ b1) {
    int e   = blockIdx.z;
    int cnt = g_cnt[e];
    int m0  = blockIdx.y * 128;
    if (m0 >= cnt) return;
    int n0  = blockIdx.x * 128;

    __shared__ __align__(16) __half As[NSTG][128 * BK];
    __shared__ __align__(16) __half Bs[NSTG][128 * BK];
    __shared__ int toks[128];

    int tid = threadIdx.x;
    {
        int m = m0 + tid;
        toks[tid] = (m < cnt) ? g_tok[e * CAP + m] : -1;
    }
    __syncthreads();

    int lane = tid & 31, warp = tid >> 5;
    int gi = lane >> 2, qk = lane & 3;
    int wm = (warp >> 1) * 64, wn = (warp & 1) * 64;

    int lr = tid;                       // loader row 0..127
    int my_tok = toks[lr];
    int abytes = (my_tok >= 0) ? 16 : 0;
    const __half* asrc = g_xh + (size_t)max(my_tok, 0) * EDIM;
    const __half* bsrc = g_w1t + ((size_t)e * HDIM + n0 + lr) * EDIM;
    unsigned so[4];
#pragma unroll
    for (int c = 0; c < 4; c++) so[c] = sw_off(lr, c);

    float acc[4][8][4];
#pragma unroll
    for (int i = 0; i < 4; i++)
#pragma unroll
        for (int j = 0; j < 8; j++)
#pragma unroll
            for (int r = 0; r < 4; r++) acc[i][j][r] = 0.f;

    auto load_stage = [&](int buf, int k0) {
#pragma unroll
        for (int c = 0; c < 4; c++) {
            cp16(As[buf] + so[c], asrc + k0 + c * 8, abytes);
            cp16(Bs[buf] + so[c], bsrc + k0 + c * 8, 16);
        }
    };

    const int KT = EDIM / BK;           // 32
    load_stage(0, 0);      cp_commit();
    load_stage(1, BK);     cp_commit();
    for (int kt = 0; kt < KT; kt++) {
        cp_wait1();
        __syncthreads();
        if (kt + 2 < KT) load_stage((kt + 2) % NSTG, (kt + 2) * BK);
        cp_commit();
        mma_stage(As[kt % NSTG], Bs[kt % NSTG], wm, wn, lane, acc);
    }

    // epilogue: +b1, exact GELU, store hid (fp16)
#pragma unroll
    for (int nj = 0; nj < 8; nj++) {
        int n = n0 + wn + nj * 8 + qk * 2;
        float b1a = b1[(size_t)e * HDIM + n];
        float b1b = b1[(size_t)e * HDIM + n + 1];
#pragma unroll
        for (int mi = 0; mi < 4; mi++) {
#pragma unroll
            for (int h = 0; h < 2; h++) {
                int m = m0 + wm + mi * 16 + gi + h * 8;
                if (m >= cnt) continue;
                float vx = gelu_exact(acc[mi][nj][h * 2 + 0] + b1a);
                float vy = gelu_exact(acc[mi][nj][h * 2 + 1] + b1b);
                *(half2*)(g_hid + ((size_t)e * CAP + m) * HDIM + n) =
                    __floats2half2_rn(vx, vy);
            }
        }
    }
}

// K3: out[tok] += w * (hid @ W2T[e]^T + b2[e])
__global__ __launch_bounds__(128, 2) void k_ffn2(const float* __restrict__ b2,
                                                 float* __restrict__ out) {
    int e   = blockIdx.z;
    int cnt = g_cnt[e];
    int m0  = blockIdx.y * 128;
    if (m0 >= cnt) return;
    int n0  = blockIdx.x * 128;

    __shared__ __align__(16) __half As[NSTG][128 * BK];
    __shared__ __align__(16) __half Bs[NSTG][128 * BK];
    __shared__ int   toks[128];
    __shared__ float wts[128];

    int tid = threadIdx.x;
    {
        int m = m0 + tid;
        bool v = (m < cnt);
        toks[tid] = v ? g_tok[e * CAP + m] : -1;
        wts[tid]  = v ? g_wgt[e * CAP + m] : 0.f;
    }
    __syncthreads();

    int mlim = cnt - m0;
    int lane = tid & 31, warp = tid >> 5;
    int gi = lane >> 2, qk = lane & 3;
    int wm = (warp >> 1) * 64, wn = (warp & 1) * 64;

    int lr = tid;
    bool mval = (lr < mlim);
    int abytes = mval ? 16 : 0;
    const __half* asrc = g_hid + ((size_t)e * CAP + m0 + (mval ? lr : 0)) * HDIM;
    const __half* bsrc = g_w2t + ((size_t)e * EDIM + n0 + lr) * HDIM;
    unsigned so[4];
#pragma unroll
    for (int c = 0; c < 4; c++) so[c] = sw_off(lr, c);

    float acc[4][8][4];
#pragma unroll
    for (int i = 0; i < 4; i++)
#pragma unroll
        for (int j = 0; j < 8; j++)
#pragma unroll
            for (int r = 0; r < 4; r++) acc[i][j][r] = 0.f;

    auto load_stage = [&](int buf, int k0) {
#pragma unroll
        for (int c = 0; c < 4; c++) {
            cp16(As[buf] + so[c], asrc + k0 + c * 8, abytes);
            cp16(Bs[buf] + so[c], bsrc + k0 + c * 8, 16);
        }
    };

    const int KT = HDIM / BK;           // 128
    load_stage(0, 0);      cp_commit();
    load_stage(1, BK);     cp_commit();
    for (int kt = 0; kt < KT; kt++) {
        cp_wait1();
        __syncthreads();
        if (kt + 2 < KT) load_stage((kt + 2) % NSTG, (kt + 2) * BK);
        cp_commit();
        mma_stage(As[kt % NSTG], Bs[kt % NSTG], wm, wn, lane, acc);
    }

#pragma unroll
    for (int nj = 0; nj < 8; nj++) {
        int n = n0 + wn + nj * 8 + qk * 2;
        float b2a = b2[(size_t)e * EDIM + n];
        float b2b = b2[(size_t)e * EDIM + n + 1];
#pragma unroll
        for (int mi = 0; mi < 4; mi++) {
#pragma unroll
            for (int h = 0; h < 2; h++) {
                int ml = wm + mi * 16 + gi + h * 8;
                int tok = toks[ml];
                if (tok < 0) continue;
                float w = wts[ml];
                float* op = out + (size_t)tok * EDIM + n;
                atomicAdd(op + 0, w * (acc[mi][nj][h * 2 + 0] + b2a));
                atomicAdd(op + 1, w * (acc[mi][nj][h * 2 + 1] + b2b));
            }
        }
    }
}

// ---------------------------------------------------------------------------
extern "C" void kernel_launch(void* const* d_in, const int* in_sizes, int n_in,
                              void* d_out, int out_size) {
    const float* x  = (const float*)d_in[0];
    const float* Wr = (const float*)d_in[1];
    const float* br = (const float*)d_in[2];
    const float* W1 = (const float*)d_in[3];
    const float* b1 = (const float*)d_in[4];
    const float* W2 = (const float*)d_in[5];
    const float* b2 = (const float*)d_in[6];
    float* out = (float*)d_out;
    (void)in_sizes; (void)n_in; (void)out_size;

    k_zero<<<4096, 256>>>(out);
    k_convx<<<(TNUM * EDIM / 2 + 255) / 256, 256>>>(x);
    {   dim3 g(HDIM / 32, EDIM / 32, NEXP);
        k_convW<0><<<g, 256>>>(W1); }
    {   dim3 g(EDIM / 32, HDIM / 32, NEXP);
        k_convW<1><<<g, 256>>>(W2); }
    k_router<<<TNUM / 8, 256>>>(x, Wr, br);
    dim3 g1(HDIM / 128, CAP / 128, NEXP);
    k_ffn1<<<g1, 128>>>(b1);
    dim3 g2(EDIM / 128, CAP / 128, NEXP);
    k_ffn2<<<g2, 128>>>(b2, out);
}

// round 11
// speedup vs baseline: 1.2918x; 1.2918x over previous
#include <cuda_runtime.h>
#include <cuda_fp16.h>
#include <math.h>

// Shapes: x[2,2048,1024] f32 -> T=4096, E=1024; Wr[1024,8]; W1[8,1024,4096];
// b1[8,4096]; W2[8,4096,1024]; b2[8,1024]; top_k=2.
#define TNUM 4096
#define EDIM 1024
#define NEXP 8
#define HDIM 4096
#define CAP  4096

// Device-global scratch. NEVER pass these as kernel args from host code.
__device__ __half g_xh [(size_t)TNUM * EDIM];
__device__ __half g_w1t[(size_t)NEXP * HDIM * EDIM];     // [e][n=H][k=E]
__device__ __half g_w2t[(size_t)NEXP * EDIM * HDIM];     // [e][n=E][k=H]
__device__ __half g_hid[(size_t)NEXP * CAP * HDIM];
__device__ int    g_cnt[NEXP];
__device__ int    g_tok[NEXP * CAP];
__device__ float  g_wgt[NEXP * CAP];

__device__ __forceinline__ float gelu_exact(float v) {
    return 0.5f * v * (1.0f + erff(v * 0.70710678118654752f));
}

__device__ __forceinline__ void mma_f16(float* c, const unsigned* a, const unsigned* b) {
    asm volatile(
        "mma.sync.aligned.m16n8k16.row.col.f32.f16.f16.f32 "
        "{%0,%1,%2,%3}, {%4,%5,%6,%7}, {%8,%9}, {%0,%1,%2,%3};"
        : "+f"(c[0]), "+f"(c[1]), "+f"(c[2]), "+f"(c[3])
        : "r"(a[0]), "r"(a[1]), "r"(a[2]), "r"(a[3]), "r"(b[0]), "r"(b[1]));
}

__device__ __forceinline__ void ldsm_x4(unsigned* d, unsigned addr) {
    asm volatile("ldmatrix.sync.aligned.m8n8.x4.shared.b16 {%0,%1,%2,%3}, [%4];"
                 : "=r"(d[0]), "=r"(d[1]), "=r"(d[2]), "=r"(d[3]) : "r"(addr));
}

__device__ __forceinline__ void cp16(void* smem, const void* gmem, int src_bytes) {
    unsigned s = (unsigned)__cvta_generic_to_shared(smem);
    asm volatile("cp.async.cg.shared.global [%0], [%1], 16, %2;\n"
                 :: "r"(s), "l"(gmem), "r"(src_bytes));
}
__device__ __forceinline__ void cp_commit() { asm volatile("cp.async.commit_group;\n"); }
__device__ __forceinline__ void cp_wait1()  { asm volatile("cp.async.wait_group 1;\n"); }

// ---------------------------------------------------------------------------
// K0: zero output + counters
// ---------------------------------------------------------------------------
__global__ void k_zero(float* __restrict__ out) {
    size_t i = (size_t)blockIdx.x * blockDim.x + threadIdx.x;
    size_t n4 = (size_t)TNUM * EDIM / 4;
    if (i < n4) ((float4*)out)[i] = make_float4(0.f, 0.f, 0.f, 0.f);
    if (blockIdx.x == 0 && threadIdx.x < NEXP) g_cnt[threadIdx.x] = 0;
}

// Kc: x f32 -> f16
__global__ void k_convx(const float* __restrict__ x) {
    size_t i = (size_t)blockIdx.x * blockDim.x + threadIdx.x;
    if (i < (size_t)TNUM * EDIM / 2) {
        float2 v = ((const float2*)x)[i];
        ((half2*)g_xh)[i] = __floats2half2_rn(v.x, v.y);
    }
}

// Kw: W [e][K][N] f32 -> WT [e][N][K] f16; destination chosen in device code.
template <int WHICH>  // 0 -> g_w1t (K=EDIM,N=HDIM), 1 -> g_w2t (K=HDIM,N=EDIM)
__global__ __launch_bounds__(256) void k_convW(const float* __restrict__ W) {
    const int K = WHICH ? HDIM : EDIM;
    const int N = WHICH ? EDIM : HDIM;
    __half* WT = WHICH ? g_w2t : g_w1t;

    __shared__ float s[32][33];
    int e = blockIdx.z;
    int k0 = blockIdx.y * 32, n0 = blockIdx.x * 32;
    const float* Wp = W + ((size_t)e * K + k0) * N + n0;
    __half* Tp = WT + ((size_t)e * N + n0) * K + k0;
    int tx = threadIdx.x & 31, ty = threadIdx.x >> 5;
#pragma unroll
    for (int i = 0; i < 32; i += 8)
        s[ty + i][tx] = Wp[(size_t)(ty + i) * N + tx];
    __syncthreads();
#pragma unroll
    for (int i = 0; i < 32; i += 8) {
        int n = ty + i;
        Tp[(size_t)n * K + tx] = __float2half_rn(s[tx][n]);
    }
}

// ---------------------------------------------------------------------------
// K1: router (exact fp32): logits, top-2, 2-way softmax, compact lists
// ---------------------------------------------------------------------------
__global__ __launch_bounds__(256) void k_router(const float* __restrict__ x,
                                                const float* __restrict__ Wr,
                                                const float* __restrict__ br) {
    int warp = (blockIdx.x * blockDim.x + threadIdx.x) >> 5;
    int lane = threadIdx.x & 31;
    if (warp >= TNUM) return;
    const float* xr = x + (size_t)warp * EDIM;

    float acc[NEXP];
#pragma unroll
    for (int n = 0; n < NEXP; n++) acc[n] = 0.f;
    for (int k = lane; k < EDIM; k += 32) {
        float xv = xr[k];
        const float4* w4 = (const float4*)(Wr + (size_t)k * NEXP);
        float4 a = w4[0], b = w4[1];
        acc[0] += xv * a.x; acc[1] += xv * a.y; acc[2] += xv * a.z; acc[3] += xv * a.w;
        acc[4] += xv * b.x; acc[5] += xv * b.y; acc[6] += xv * b.z; acc[7] += xv * b.w;
    }
#pragma unroll
    for (int n = 0; n < NEXP; n++)
#pragma unroll
        for (int o = 16; o > 0; o >>= 1)
            acc[n] += __shfl_xor_sync(0xffffffffu, acc[n], o);
    if (lane == 0) {
        float l[NEXP];
#pragma unroll
        for (int n = 0; n < NEXP; n++) l[n] = acc[n] + br[n];
        int i0 = 0;
#pragma unroll
        for (int n = 1; n < NEXP; n++) if (l[n] > l[i0]) i0 = n;
        int i1 = -1;
#pragma unroll
        for (int n = 0; n < NEXP; n++) {
            if (n == i0) continue;
            if (i1 < 0 || l[n] > l[i1]) i1 = n;
        }
        float d  = __expf(l[i1] - l[i0]);
        float w0 = 1.f / (1.f + d);
        float w1 = d * w0;
        int s0 = atomicAdd(&g_cnt[i0], 1);
        g_tok[i0 * CAP + s0] = warp;  g_wgt[i0 * CAP + s0] = w0;
        int s1 = atomicAdd(&g_cnt[i1], 1);
        g_tok[i1 * CAP + s1] = warp;  g_wgt[i1 * CAP + s1] = w1;
    }
}

// ---------------------------------------------------------------------------
// fp16 grouped GEMMs: 128x128 tile, BK=64, 256 thr (8 warps 2x4), warp 64x32,
// mma m16n8k16, ldmatrix, 3-stage cp.async pipeline (dynamic smem, 96 KB).
// Unpadded 128B rows, XOR chunk swizzle pc = c ^ (r&7): stores + all ldmatrix
// phases hit 8 distinct 16B bank groups (conflict-free, verified).
// ---------------------------------------------------------------------------
#define BK 64
#define NSTG 3
#define STGH (128 * BK)                 // halves per stage buffer (16 KB)

__device__ __forceinline__ unsigned sw_off(int r, int c) {  // offset in halves
    return (unsigned)(r * BK + ((c ^ (r & 7)) << 3));
}

__device__ __forceinline__ void mma_stage(const __half* As, const __half* Bs,
                                          int wm, int wn, int lane,
                                          float acc[4][4][4]) {
    unsigned abase = (unsigned)__cvta_generic_to_shared(As);
    unsigned bbase = (unsigned)__cvta_generic_to_shared(Bs);
    int arow = lane & 15;
    int brow = ((lane >> 4) << 3) + (lane & 7);
#pragma unroll
    for (int ks = 0; ks < BK; ks += 16) {
        unsigned a[4][4], b[2][4];
        int achunk = (ks >> 3) + (lane >> 4);
        int bchunk = (ks >> 3) + ((lane >> 3) & 1);
#pragma unroll
        for (int mi = 0; mi < 4; mi++)
            ldsm_x4(a[mi], abase + 2u * sw_off(wm + mi * 16 + arow, achunk));
#pragma unroll
        for (int nj2 = 0; nj2 < 2; nj2++)
            ldsm_x4(b[nj2], bbase + 2u * sw_off(wn + nj2 * 16 + brow, bchunk));
#pragma unroll
        for (int mi = 0; mi < 4; mi++)
#pragma unroll
            for (int nj = 0; nj < 4; nj++)
                mma_f16(acc[mi][nj], a[mi], &b[nj >> 1][(nj & 1) * 2]);
    }
}

// K2: hid = gelu(gather(x_h) @ W1T[e]^T + b1[e])
__global__ __launch_bounds__(256, 2) void k_ffn1(const float* __restrict__ b1) {
    int e   = blockIdx.z;
    int cnt = g_cnt[e];
    int m0  = blockIdx.y * 128;
    if (m0 >= cnt) return;
    int n0  = blockIdx.x * 128;

    extern __shared__ __align__(16) __half dynsm[];
    __half* As = dynsm;                 // NSTG * STGH
    __half* Bs = dynsm + NSTG * STGH;   // NSTG * STGH
    __shared__ int toks[128];

    int tid = threadIdx.x;
    if (tid < 128) {
        int m = m0 + tid;
        toks[tid] = (m < cnt) ? g_tok[e * CAP + m] : -1;
    }
    __syncthreads();

    int lane = tid & 31, warp = tid >> 5;
    int gi = lane >> 2, qk = lane & 3;
    int wm = (warp >> 2) * 64, wn = (warp & 3) * 32;

    int lr = tid >> 1, c0 = (tid & 1) * 4;   // row, first of 4 chunks
    int my_tok = toks[lr];
    int abytes = (my_tok >= 0) ? 16 : 0;
    const __half* asrc = g_xh + (size_t)max(my_tok, 0) * EDIM;
    const __half* bsrc = g_w1t + ((size_t)e * HDIM + n0 + lr) * EDIM;
    unsigned so[4];
#pragma unroll
    for (int c = 0; c < 4; c++) so[c] = sw_off(lr, c0 + c);

    float acc[4][4][4];
#pragma unroll
    for (int i = 0; i < 4; i++)
#pragma unroll
        for (int j = 0; j < 4; j++)
#pragma unroll
            for (int r = 0; r < 4; r++) acc[i][j][r] = 0.f;

    auto load_stage = [&](int buf, int k0) {
#pragma unroll
        for (int c = 0; c < 4; c++) {
            cp16(As + buf * STGH + so[c], asrc + k0 + (c0 + c) * 8, abytes);
            cp16(Bs + buf * STGH + so[c], bsrc + k0 + (c0 + c) * 8, 16);
        }
    };

    const int KT = EDIM / BK;           // 16
    load_stage(0, 0);      cp_commit();
    load_stage(1, BK);     cp_commit();
    for (int kt = 0; kt < KT; kt++) {
        cp_wait1();
        __syncthreads();
        if (kt + 2 < KT) load_stage((kt + 2) % NSTG, (kt + 2) * BK);
        cp_commit();
        mma_stage(As + (kt % NSTG) * STGH, Bs + (kt % NSTG) * STGH,
                  wm, wn, lane, acc);
    }

    // epilogue: +b1, exact GELU, store hid (fp16)
#pragma unroll
    for (int nj = 0; nj < 4; nj++) {
        int n = n0 + wn + nj * 8 + qk * 2;
        float b1a = b1[(size_t)e * HDIM + n];
        float b1b = b1[(size_t)e * HDIM + n + 1];
#pragma unroll
        for (int mi = 0; mi < 4; mi++) {
#pragma unroll
            for (int h = 0; h < 2; h++) {
                int m = m0 + wm + mi * 16 + gi + h * 8;
                if (m >= cnt) continue;
                float vx = gelu_exact(acc[mi][nj][h * 2 + 0] + b1a);
                float vy = gelu_exact(acc[mi][nj][h * 2 + 1] + b1b);
                *(half2*)(g_hid + ((size_t)e * CAP + m) * HDIM + n) =
                    __floats2half2_rn(vx, vy);
            }
        }
    }
}

// K3: out[tok] += w * (hid @ W2T[e]^T + b2[e])
__global__ __launch_bounds__(256, 2) void k_ffn2(const float* __restrict__ b2,
                                                 float* __restrict__ out) {
    int e   = blockIdx.z;
    int cnt = g_cnt[e];
    int m0  = blockIdx.y * 128;
    if (m0 >= cnt) return;
    int n0  = blockIdx.x * 128;

    extern __shared__ __align__(16) __half dynsm[];
    __half* As = dynsm;
    __half* Bs = dynsm + NSTG * STGH;
    __shared__ int   toks[128];
    __shared__ float wts[128];

    int tid = threadIdx.x;
    if (tid < 128) {
        int m = m0 + tid;
        bool v = (m < cnt);
        toks[tid] = v ? g_tok[e * CAP + m] : -1;
        wts[tid]  = v ? g_wgt[e * CAP + m] : 0.f;
    }
    __syncthreads();

    int mlim = cnt - m0;
    int lane = tid & 31, warp = tid >> 5;
    int gi = lane >> 2, qk = lane & 3;
    int wm = (warp >> 2) * 64, wn = (warp & 3) * 32;

    int lr = tid >> 1, c0 = (tid & 1) * 4;
    bool mval = (lr < mlim);
    int abytes = mval ? 16 : 0;
    const __half* asrc = g_hid + ((size_t)e * CAP + m0 + (mval ? lr : 0)) * HDIM;
    const __half* bsrc = g_w2t + ((size_t)e * EDIM + n0 + lr) * HDIM;
    unsigned so[4];
#pragma unroll
    for (int c = 0; c < 4; c++) so[c] = sw_off(lr, c0 + c);

    float acc[4][4][4];
#pragma unroll
    for (int i = 0; i < 4; i++)
#pragma unroll
        for (int j = 0; j < 4; j++)
#pragma unroll
            for (int r = 0; r < 4; r++) acc[i][j][r] = 0.f;

    auto load_stage = [&](int buf, int k0) {
#pragma unroll
        for (int c = 0; c < 4; c++) {
            cp16(As + buf * STGH + so[c], asrc + k0 + (c0 + c) * 8, abytes);
            cp16(Bs + buf * STGH + so[c], bsrc + k0 + (c0 + c) * 8, 16);
        }
    };

    const int KT = HDIM / BK;           // 64
    load_stage(0, 0);      cp_commit();
    load_stage(1, BK);     cp_commit();
    for (int kt = 0; kt < KT; kt++) {
        cp_wait1();
        __syncthreads();
        if (kt + 2 < KT) load_stage((kt + 2) % NSTG, (kt + 2) * BK);
        cp_commit();
        mma_stage(As + (kt % NSTG) * STGH, Bs + (kt % NSTG) * STGH,
                  wm, wn, lane, acc);
    }

#pragma unroll
    for (int nj = 0; nj < 4; nj++) {
        int n = n0 + wn + nj * 8 + qk * 2;
        float b2a = b2[(size_t)e * EDIM + n];
        float b2b = b2[(size_t)e * EDIM + n + 1];
#pragma unroll
        for (int mi = 0; mi < 4; mi++) {
#pragma unroll
            for (int h = 0; h < 2; h++) {
                int ml = wm + mi * 16 + gi + h * 8;
                int tok = toks[ml];
                if (tok < 0) continue;
                float w = wts[ml];
                float* op = out + (size_t)tok * EDIM + n;
                atomicAdd(op + 0, w * (acc[mi][nj][h * 2 + 0] + b2a));
                atomicAdd(op + 1, w * (acc[mi][nj][h * 2 + 1] + b2b));
            }
        }
    }
}

// ---------------------------------------------------------------------------
extern "C" void kernel_launch(void* const* d_in, const int* in_sizes, int n_in,
                              void* d_out, int out_size) {
    const float* x  = (const float*)d_in[0];
    const float* Wr = (const float*)d_in[1];
    const float* br = (const float*)d_in[2];
    const float* W1 = (const float*)d_in[3];
    const float* b1 = (const float*)d_in[4];
    const float* W2 = (const float*)d_in[5];
    const float* b2 = (const float*)d_in[6];
    float* out = (float*)d_out;
    (void)in_sizes; (void)n_in; (void)out_size;

    const int dynsz = 2 * NSTG * STGH * (int)sizeof(__half);   // 96 KB
    static int attr_done = 0;
    if (!attr_done) {
        cudaFuncSetAttribute(k_ffn1, cudaFuncAttributeMaxDynamicSharedMemorySize, dynsz);
        cudaFuncSetAttribute(k_ffn2, cudaFuncAttributeMaxDynamicSharedMemorySize, dynsz);
        attr_done = 1;
    }

    k_zero<<<4096, 256>>>(out);
    k_convx<<<(TNUM * EDIM / 2 + 255) / 256, 256>>>(x);
    {   dim3 g(HDIM / 32, EDIM / 32, NEXP);
        k_convW<0><<<g, 256>>>(W1); }
    {   dim3 g(EDIM / 32, HDIM / 32, NEXP);
        k_convW<1><<<g, 256>>>(W2); }
    k_router<<<TNUM / 8, 256>>>(x, Wr, br);
    dim3 g1(HDIM / 128, CAP / 128, NEXP);
    k_ffn1<<<g1, 256, dynsz>>>(b1);
    dim3 g2(EDIM / 128, CAP / 128, NEXP);
    k_ffn2<<<g2, 256, dynsz>>>(b2, out);
}

// round 12
// speedup vs baseline: 1.4086x; 1.0904x over previous
#include <cuda_runtime.h>
#include <cuda_fp16.h>
#include <math.h>

// Shapes: x[2,2048,1024] f32 -> T=4096, E=1024; Wr[1024,8]; W1[8,1024,4096];
// b1[8,4096]; W2[8,4096,1024]; b2[8,1024]; top_k=2.
#define TNUM 4096
#define EDIM 1024
#define NEXP 8
#define HDIM 4096
#define CAP  4096

// Device-global scratch. NEVER pass these as kernel args from host code.
__device__ __half g_xh [(size_t)TNUM * EDIM];
__device__ __half g_w1t[(size_t)NEXP * HDIM * EDIM];     // [e][n=H][k=E]
__device__ __half g_w2t[(size_t)NEXP * EDIM * HDIM];     // [e][n=E][k=H]
__device__ __half g_hid[(size_t)NEXP * CAP * HDIM];
__device__ int    g_cnt[NEXP];
__device__ int    g_tok[NEXP * CAP];
__device__ float  g_wgt[NEXP * CAP];

__device__ __forceinline__ float gelu_exact(float v) {
    return 0.5f * v * (1.0f + erff(v * 0.70710678118654752f));
}

__device__ __forceinline__ void mma_f16(float* c, const unsigned* a, const unsigned* b) {
    asm volatile(
        "mma.sync.aligned.m16n8k16.row.col.f32.f16.f16.f32 "
        "{%0,%1,%2,%3}, {%4,%5,%6,%7}, {%8,%9}, {%0,%1,%2,%3};"
        : "+f"(c[0]), "+f"(c[1]), "+f"(c[2]), "+f"(c[3])
        : "r"(a[0]), "r"(a[1]), "r"(a[2]), "r"(a[3]), "r"(b[0]), "r"(b[1]));
}

__device__ __forceinline__ void ldsm_x4(unsigned* d, unsigned addr) {
    asm volatile("ldmatrix.sync.aligned.m8n8.x4.shared.b16 {%0,%1,%2,%3}, [%4];"
                 : "=r"(d[0]), "=r"(d[1]), "=r"(d[2]), "=r"(d[3]) : "r"(addr));
}

__device__ __forceinline__ void cp16(void* smem, const void* gmem, int src_bytes) {
    unsigned s = (unsigned)__cvta_generic_to_shared(smem);
    asm volatile("cp.async.cg.shared.global [%0], [%1], 16, %2;\n"
                 :: "r"(s), "l"(gmem), "r"(src_bytes));
}
__device__ __forceinline__ void cp_commit() { asm volatile("cp.async.commit_group;\n"); }
__device__ __forceinline__ void cp_wait2()  { asm volatile("cp.async.wait_group 2;\n"); }

// ---------------------------------------------------------------------------
// K0: zero output + counters
// ---------------------------------------------------------------------------
__global__ void k_zero(float* __restrict__ out) {
    size_t i = (size_t)blockIdx.x * blockDim.x + threadIdx.x;
    size_t n4 = (size_t)TNUM * EDIM / 4;
    if (i < n4) ((float4*)out)[i] = make_float4(0.f, 0.f, 0.f, 0.f);
    if (blockIdx.x == 0 && threadIdx.x < NEXP) g_cnt[threadIdx.x] = 0;
}

// Kc: x f32 -> f16
__global__ void k_convx(const float* __restrict__ x) {
    size_t i = (size_t)blockIdx.x * blockDim.x + threadIdx.x;
    if (i < (size_t)TNUM * EDIM / 2) {
        float2 v = ((const float2*)x)[i];
        ((half2*)g_xh)[i] = __floats2half2_rn(v.x, v.y);
    }
}

// Kw: W [e][K][N] f32 -> WT [e][N][K] f16; destination chosen in device code.
template <int WHICH>  // 0 -> g_w1t (K=EDIM,N=HDIM), 1 -> g_w2t (K=HDIM,N=EDIM)
__global__ __launch_bounds__(256) void k_convW(const float* __restrict__ W) {
    const int K = WHICH ? HDIM : EDIM;
    const int N = WHICH ? EDIM : HDIM;
    __half* WT = WHICH ? g_w2t : g_w1t;

    __shared__ float s[32][33];
    int e = blockIdx.z;
    int k0 = blockIdx.y * 32, n0 = blockIdx.x * 32;
    const float* Wp = W + ((size_t)e * K + k0) * N + n0;
    __half* Tp = WT + ((size_t)e * N + n0) * K + k0;
    int tx = threadIdx.x & 31, ty = threadIdx.x >> 5;
#pragma unroll
    for (int i = 0; i < 32; i += 8)
        s[ty + i][tx] = Wp[(size_t)(ty + i) * N + tx];
    __syncthreads();
#pragma unroll
    for (int i = 0; i < 32; i += 8) {
        int n = ty + i;
        Tp[(size_t)n * K + tx] = __float2half_rn(s[tx][n]);
    }
}

// ---------------------------------------------------------------------------
// K1: router (exact fp32): logits, top-2, 2-way softmax, compact lists
// ---------------------------------------------------------------------------
__global__ __launch_bounds__(256) void k_router(const float* __restrict__ x,
                                                const float* __restrict__ Wr,
                                                const float* __restrict__ br) {
    int warp = (blockIdx.x * blockDim.x + threadIdx.x) >> 5;
    int lane = threadIdx.x & 31;
    if (warp >= TNUM) return;
    const float* xr = x + (size_t)warp * EDIM;

    float acc[NEXP];
#pragma unroll
    for (int n = 0; n < NEXP; n++) acc[n] = 0.f;
    for (int k = lane; k < EDIM; k += 32) {
        float xv = xr[k];
        const float4* w4 = (const float4*)(Wr + (size_t)k * NEXP);
        float4 a = w4[0], b = w4[1];
        acc[0] += xv * a.x; acc[1] += xv * a.y; acc[2] += xv * a.z; acc[3] += xv * a.w;
        acc[4] += xv * b.x; acc[5] += xv * b.y; acc[6] += xv * b.z; acc[7] += xv * b.w;
    }
#pragma unroll
    for (int n = 0; n < NEXP; n++)
#pragma unroll
        for (int o = 16; o > 0; o >>= 1)
            acc[n] += __shfl_xor_sync(0xffffffffu, acc[n], o);
    if (lane == 0) {
        float l[NEXP];
#pragma unroll
        for (int n = 0; n < NEXP; n++) l[n] = acc[n] + br[n];
        int i0 = 0;
#pragma unroll
        for (int n = 1; n < NEXP; n++) if (l[n] > l[i0]) i0 = n;
        int i1 = -1;
#pragma unroll
        for (int n = 0; n < NEXP; n++) {
            if (n == i0) continue;
            if (i1 < 0 || l[n] > l[i1]) i1 = n;
        }
        float d  = __expf(l[i1] - l[i0]);
        float w0 = 1.f / (1.f + d);
        float w1 = d * w0;
        int s0 = atomicAdd(&g_cnt[i0], 1);
        g_tok[i0 * CAP + s0] = warp;  g_wgt[i0 * CAP + s0] = w0;
        int s1 = atomicAdd(&g_cnt[i1], 1);
        g_tok[i1 * CAP + s1] = warp;  g_wgt[i1 * CAP + s1] = w1;
    }
}

// ---------------------------------------------------------------------------
// fp16 grouped GEMMs: 128x128 tile, BK=32, 256 thr (8 warps 2x4), warp 64x32,
// mma m16n8k16, ldmatrix, 4-stage cp.async pipeline (wait_group 2; next-stage
// loads issued before the wait). Unpadded 64B rows, XOR chunk swizzle
// pc = c ^ ((r>>1)&3): stores and all LDSM phases conflict-free.
// ---------------------------------------------------------------------------
#define BK 32
#define NSTG 4

__device__ __forceinline__ unsigned sw_off(int r, int c) {  // offset in halves
    return (unsigned)(r * BK + ((c ^ ((r >> 1) & 3)) << 3));
}

__device__ __forceinline__ void mma_stage(const __half* As, const __half* Bs,
                                          int wm, int wn, int lane,
                                          float acc[4][4][4]) {
    unsigned abase = (unsigned)__cvta_generic_to_shared(As);
    unsigned bbase = (unsigned)__cvta_generic_to_shared(Bs);
    int arow = lane & 15;
    int brow = ((lane >> 4) << 3) + (lane & 7);
#pragma unroll
    for (int ks = 0; ks < BK; ks += 16) {
        unsigned a[4][4], b[2][4];
        int achunk = (ks >> 3) + (lane >> 4);
        int bchunk = (ks >> 3) + ((lane >> 3) & 1);
#pragma unroll
        for (int mi = 0; mi < 4; mi++)
            ldsm_x4(a[mi], abase + 2u * sw_off(wm + mi * 16 + arow, achunk));
#pragma unroll
        for (int nj2 = 0; nj2 < 2; nj2++)
            ldsm_x4(b[nj2], bbase + 2u * sw_off(wn + nj2 * 16 + brow, bchunk));
#pragma unroll
        for (int mi = 0; mi < 4; mi++)
#pragma unroll
            for (int nj = 0; nj < 4; nj++)
                mma_f16(acc[mi][nj], a[mi], &b[nj >> 1][(nj & 1) * 2]);
    }
}

// K2: hid = gelu(gather(x_h) @ W1T[e]^T + b1[e])
__global__ __launch_bounds__(256, 2) void k_ffn1(const float* __restrict__ b1) {
    int e   = blockIdx.z;
    int cnt = g_cnt[e];
    int m0  = blockIdx.y * 128;
    if (m0 >= cnt) return;
    int n0  = blockIdx.x * 128;

    __shared__ __align__(16) __half As[NSTG][128 * BK];
    __shared__ __align__(16) __half Bs[NSTG][128 * BK];
    __shared__ int toks[128];

    int tid = threadIdx.x;
    if (tid < 128) {
        int m = m0 + tid;
        toks[tid] = (m < cnt) ? g_tok[e * CAP + m] : -1;
    }
    __syncthreads();

    int lane = tid & 31, warp = tid >> 5;
    int gi = lane >> 2, qk = lane & 3;
    int wm = (warp >> 2) * 64, wn = (warp & 3) * 32;

    int lr = tid >> 1, c0 = (tid & 1) * 2;
    int my_tok = toks[lr];
    int abytes = (my_tok >= 0) ? 16 : 0;
    const __half* asrc = g_xh + (size_t)max(my_tok, 0) * EDIM;
    const __half* bsrc = g_w1t + ((size_t)e * HDIM + n0 + lr) * EDIM;
    unsigned so0 = sw_off(lr, c0), so1 = sw_off(lr, c0 + 1);

    float acc[4][4][4];
#pragma unroll
    for (int i = 0; i < 4; i++)
#pragma unroll
        for (int j = 0; j < 4; j++)
#pragma unroll
            for (int r = 0; r < 4; r++) acc[i][j][r] = 0.f;

    auto load_stage = [&](int buf, int k0) {
        cp16(As[buf] + so0, asrc + k0 + c0 * 8,       abytes);
        cp16(As[buf] + so1, asrc + k0 + c0 * 8 + 8,   abytes);
        cp16(Bs[buf] + so0, bsrc + k0 + c0 * 8,       16);
        cp16(Bs[buf] + so1, bsrc + k0 + c0 * 8 + 8,   16);
    };

    const int KT = EDIM / BK;       // 32
    load_stage(0, 0);      cp_commit();
    load_stage(1, BK);     cp_commit();
    for (int kt = 0; kt < KT; kt++) {
        if (kt + 2 < KT) load_stage((kt + 2) % NSTG, (kt + 2) * BK);
        cp_commit();                 // uniform group count (empty ok)
        cp_wait2();                  // stage kt resident; kt+1,kt+2 may pend
        __syncthreads();
        mma_stage(As[kt % NSTG], Bs[kt % NSTG], wm, wn, lane, acc);
    }

    // epilogue: +b1, exact GELU, store hid (fp16)
#pragma unroll
    for (int nj = 0; nj < 4; nj++) {
        int n = n0 + wn + nj * 8 + qk * 2;
        float b1a = b1[(size_t)e * HDIM + n];
        float b1b = b1[(size_t)e * HDIM + n + 1];
#pragma unroll
        for (int mi = 0; mi < 4; mi++) {
#pragma unroll
            for (int h = 0; h < 2; h++) {
                int m = m0 + wm + mi * 16 + gi + h * 8;
                if (m >= cnt) continue;
                float vx = gelu_exact(acc[mi][nj][h * 2 + 0] + b1a);
                float vy = gelu_exact(acc[mi][nj][h * 2 + 1] + b1b);
                *(half2*)(g_hid + ((size_t)e * CAP + m) * HDIM + n) =
                    __floats2half2_rn(vx, vy);
            }
        }
    }
}

// K3: out[tok] += w * (hid @ W2T[e]^T + b2[e])
__global__ __launch_bounds__(256, 2) void k_ffn2(const float* __restrict__ b2,
                                                 float* __restrict__ out) {
    int e   = blockIdx.z;
    int cnt = g_cnt[e];
    int m0  = blockIdx.y * 128;
    if (m0 >= cnt) return;
    int n0  = blockIdx.x * 128;

    __shared__ __align__(16) __half As[NSTG][128 * BK];
    __shared__ __align__(16) __half Bs[NSTG][128 * BK];
    __shared__ int   toks[128];
    __shared__ float wts[128];

    int tid = threadIdx.x;
    if (tid < 128) {
        int m = m0 + tid;
        bool v = (m < cnt);
        toks[tid] = v ? g_tok[e * CAP + m] : -1;
        wts[tid]  = v ? g_wgt[e * CAP + m] : 0.f;
    }
    __syncthreads();

    int mlim = cnt - m0;
    int lane = tid & 31, warp = tid >> 5;
    int gi = lane >> 2, qk = lane & 3;
    int wm = (warp >> 2) * 64, wn = (warp & 3) * 32;

    int lr = tid >> 1, c0 = (tid & 1) * 2;
    bool mval = (lr < mlim);
    int abytes = mval ? 16 : 0;
    const __half* asrc = g_hid + ((size_t)e * CAP + m0 + (mval ? lr : 0)) * HDIM;
    const __half* bsrc = g_w2t + ((size_t)e * EDIM + n0 + lr) * HDIM;
    unsigned so0 = sw_off(lr, c0), so1 = sw_off(lr, c0 + 1);

    float acc[4][4][4];
#pragma unroll
    for (int i = 0; i < 4; i++)
#pragma unroll
        for (int j = 0; j < 4; j++)
#pragma unroll
            for (int r = 0; r < 4; r++) acc[i][j][r] = 0.f;

    auto load_stage = [&](int buf, int k0) {
        cp16(As[buf] + so0, asrc + k0 + c0 * 8,       abytes);
        cp16(As[buf] + so1, asrc + k0 + c0 * 8 + 8,   abytes);
        cp16(Bs[buf] + so0, bsrc + k0 + c0 * 8,       16);
        cp16(Bs[buf] + so1, bsrc + k0 + c0 * 8 + 8,   16);
    };

    const int KT = HDIM / BK;       // 128
    load_stage(0, 0);      cp_commit();
    load_stage(1, BK);     cp_commit();
    for (int kt = 0; kt < KT; kt++) {
        if (kt + 2 < KT) load_stage((kt + 2) % NSTG, (kt + 2) * BK);
        cp_commit();
        cp_wait2();
        __syncthreads();
        mma_stage(As[kt % NSTG], Bs[kt % NSTG], wm, wn, lane, acc);
    }

#pragma unroll
    for (int nj = 0; nj < 4; nj++) {
        int n = n0 + wn + nj * 8 + qk * 2;
        float b2a = b2[(size_t)e * EDIM + n];
        float b2b = b2[(size_t)e * EDIM + n + 1];
#pragma unroll
        for (int mi = 0; mi < 4; mi++) {
#pragma unroll
            for (int h = 0; h < 2; h++) {
                int ml = wm + mi * 16 + gi + h * 8;
                int tok = toks[ml];
                if (tok < 0) continue;
                float w = wts[ml];
                float* op = out + (size_t)tok * EDIM + n;
                atomicAdd(op + 0, w * (acc[mi][nj][h * 2 + 0] + b2a));
                atomicAdd(op + 1, w * (acc[mi][nj][h * 2 + 1] + b2b));
            }
        }
    }
}

// ---------------------------------------------------------------------------
extern "C" void kernel_launch(void* const* d_in, const int* in_sizes, int n_in,
                              void* d_out, int out_size) {
    const float* x  = (const float*)d_in[0];
    const float* Wr = (const float*)d_in[1];
    const float* br = (const float*)d_in[2];
    const float* W1 = (const float*)d_in[3];
    const float* b1 = (const float*)d_in[4];
    const float* W2 = (const float*)d_in[5];
    const float* b2 = (const float*)d_in[6];
    float* out = (float*)d_out;
    (void)in_sizes; (void)n_in; (void)out_size;

    k_zero<<<4096, 256>>>(out);
    k_convx<<<(TNUM * EDIM / 2 + 255) / 256, 256>>>(x);
    {   dim3 g(HDIM / 32, EDIM / 32, NEXP);
        k_convW<0><<<g, 256>>>(W1); }
    {   dim3 g(EDIM / 32, HDIM / 32, NEXP);
        k_convW<1><<<g, 256>>>(W2); }
    k_router<<<TNUM / 8, 256>>>(x, Wr, br);
    dim3 g1(HDIM / 128, CAP / 128, NEXP);
    k_ffn1<<<g1, 256>>>(b1);
    dim3 g2(EDIM / 128, CAP / 128, NEXP);
    k_ffn2<<<g2, 256>>>(b2, out);
}

// round 13
// speedup vs baseline: 1.4755x; 1.0475x over previous
#include <cuda_runtime.h>
#include <cuda_fp16.h>
#include <math.h>

// Shapes: x[2,2048,1024] f32 -> T=4096, E=1024; Wr[1024,8]; W1[8,1024,4096];
// b1[8,4096]; W2[8,4096,1024]; b2[8,1024]; top_k=2.
#define TNUM 4096
#define EDIM 1024
#define NEXP 8
#define HDIM 4096
#define CAP  4096

// Device-global scratch. NEVER pass these as kernel args from host code.
__device__ __half g_xh [(size_t)TNUM * EDIM];
__device__ __half g_w1t[(size_t)NEXP * HDIM * EDIM];     // [e][n=H][k=E]
__device__ __half g_w2t[(size_t)NEXP * EDIM * HDIM];     // [e][n=E][k=H]
__device__ __half g_hid[(size_t)NEXP * CAP * HDIM];
__device__ int    g_cnt[NEXP];
__device__ int    g_tok[NEXP * CAP];
__device__ float  g_wgt[NEXP * CAP];

__device__ __forceinline__ float gelu_exact(float v) {
    return 0.5f * v * (1.0f + erff(v * 0.70710678118654752f));
}

__device__ __forceinline__ void mma_f16(float* c, const unsigned* a, const unsigned* b) {
    asm volatile(
        "mma.sync.aligned.m16n8k16.row.col.f32.f16.f16.f32 "
        "{%0,%1,%2,%3}, {%4,%5,%6,%7}, {%8,%9}, {%0,%1,%2,%3};"
        : "+f"(c[0]), "+f"(c[1]), "+f"(c[2]), "+f"(c[3])
        : "r"(a[0]), "r"(a[1]), "r"(a[2]), "r"(a[3]), "r"(b[0]), "r"(b[1]));
}

__device__ __forceinline__ void ldsm_x4(unsigned* d, unsigned addr) {
    asm volatile("ldmatrix.sync.aligned.m8n8.x4.shared.b16 {%0,%1,%2,%3}, [%4];"
                 : "=r"(d[0]), "=r"(d[1]), "=r"(d[2]), "=r"(d[3]) : "r"(addr));
}

__device__ __forceinline__ void cp16(void* smem, const void* gmem, int src_bytes) {
    unsigned s = (unsigned)__cvta_generic_to_shared(smem);
    asm volatile("cp.async.cg.shared.global [%0], [%1], 16, %2;\n"
                 :: "r"(s), "l"(gmem), "r"(src_bytes));
}
__device__ __forceinline__ void cp_commit() { asm volatile("cp.async.commit_group;\n"); }
__device__ __forceinline__ void cp_wait2()  { asm volatile("cp.async.wait_group 2;\n"); }

// ---------------------------------------------------------------------------
// K_init: zero expert counters (router dependency)
// ---------------------------------------------------------------------------
__global__ void k_init() {
    if (threadIdx.x < NEXP) g_cnt[threadIdx.x] = 0;
}

// K0: zero output
__global__ void k_zero(float* __restrict__ out) {
    size_t i = (size_t)blockIdx.x * blockDim.x + threadIdx.x;
    size_t n4 = (size_t)TNUM * EDIM / 4;
    if (i < n4) ((float4*)out)[i] = make_float4(0.f, 0.f, 0.f, 0.f);
}

// Kc: x f32 -> f16
__global__ void k_convx(const float* __restrict__ x) {
    size_t i = (size_t)blockIdx.x * blockDim.x + threadIdx.x;
    if (i < (size_t)TNUM * EDIM / 2) {
        float2 v = ((const float2*)x)[i];
        ((half2*)g_xh)[i] = __floats2half2_rn(v.x, v.y);
    }
}

// Kw: W [e][K][N] f32 -> WT [e][N][K] f16; 64k x 32n tile, half2 stores
// (full 128B store transactions; round-11 version was 64B/warp).
template <int WHICH>  // 0 -> g_w1t (K=EDIM,N=HDIM), 1 -> g_w2t (K=HDIM,N=EDIM)
__global__ __launch_bounds__(256) void k_convW(const float* __restrict__ W) {
    const int K = WHICH ? HDIM : EDIM;
    const int N = WHICH ? EDIM : HDIM;
    __half* WT = WHICH ? g_w2t : g_w1t;

    __shared__ float s[64][33];
    int e = blockIdx.z;
    int k0 = blockIdx.y * 64, n0 = blockIdx.x * 32;
    const float* Wp = W + ((size_t)e * K + k0) * N + n0;
    __half* Tp = WT + ((size_t)e * N + n0) * K + k0;
    int tx = threadIdx.x & 31, ty = threadIdx.x >> 5;
#pragma unroll
    for (int i = 0; i < 8; i++)
        s[ty + i * 8][tx] = Wp[(size_t)(ty + i * 8) * N + tx];
    __syncthreads();
#pragma unroll
    for (int i = 0; i < 4; i++) {
        int n = ty + i * 8;
        half2 h = __floats2half2_rn(s[2 * tx][n], s[2 * tx + 1][n]);
        *(half2*)(Tp + (size_t)n * K + 2 * tx) = h;
    }
}

// ---------------------------------------------------------------------------
// K1: router (exact fp32): logits, top-2, 2-way softmax, compact lists
// ---------------------------------------------------------------------------
__global__ __launch_bounds__(256) void k_router(const float* __restrict__ x,
                                                const float* __restrict__ Wr,
                                                const float* __restrict__ br) {
    int warp = (blockIdx.x * blockDim.x + threadIdx.x) >> 5;
    int lane = threadIdx.x & 31;
    if (warp >= TNUM) return;
    const float* xr = x + (size_t)warp * EDIM;

    float acc[NEXP];
#pragma unroll
    for (int n = 0; n < NEXP; n++) acc[n] = 0.f;
    for (int k = lane; k < EDIM; k += 32) {
        float xv = xr[k];
        const float4* w4 = (const float4*)(Wr + (size_t)k * NEXP);
        float4 a = w4[0], b = w4[1];
        acc[0] += xv * a.x; acc[1] += xv * a.y; acc[2] += xv * a.z; acc[3] += xv * a.w;
        acc[4] += xv * b.x; acc[5] += xv * b.y; acc[6] += xv * b.z; acc[7] += xv * b.w;
    }
#pragma unroll
    for (int n = 0; n < NEXP; n++)
#pragma unroll
        for (int o = 16; o > 0; o >>= 1)
            acc[n] += __shfl_xor_sync(0xffffffffu, acc[n], o);
    if (lane == 0) {
        float l[NEXP];
#pragma unroll
        for (int n = 0; n < NEXP; n++) l[n] = acc[n] + br[n];
        int i0 = 0;
#pragma unroll
        for (int n = 1; n < NEXP; n++) if (l[n] > l[i0]) i0 = n;
        int i1 = -1;
#pragma unroll
        for (int n = 0; n < NEXP; n++) {
            if (n == i0) continue;
            if (i1 < 0 || l[n] > l[i1]) i1 = n;
        }
        float d  = __expf(l[i1] - l[i0]);
        float w0 = 1.f / (1.f + d);
        float w1 = d * w0;
        int s0 = atomicAdd(&g_cnt[i0], 1);
        g_tok[i0 * CAP + s0] = warp;  g_wgt[i0 * CAP + s0] = w0;
        int s1 = atomicAdd(&g_cnt[i1], 1);
        g_tok[i1 * CAP + s1] = warp;  g_wgt[i1 * CAP + s1] = w1;
    }
}

// ---------------------------------------------------------------------------
// fp16 grouped GEMMs: 128x128 tile, BK=32, 256 thr (8 warps 2x4), warp 64x32,
// mma m16n8k16, ldmatrix, 4-stage cp.async pipeline (wait_group 2; next-stage
// loads issued before the wait). Unpadded 64B rows, XOR chunk swizzle
// pc = c ^ ((r>>1)&3): stores and all LDSM phases conflict-free.
// ---------------------------------------------------------------------------
#define BK 32
#define NSTG 4

__device__ __forceinline__ unsigned sw_off(int r, int c) {  // offset in halves
    return (unsigned)(r * BK + ((c ^ ((r >> 1) & 3)) << 3));
}

__device__ __forceinline__ void mma_stage(const __half* As, const __half* Bs,
                                          int wm, int wn, int lane,
                                          float acc[4][4][4]) {
    unsigned abase = (unsigned)__cvta_generic_to_shared(As);
    unsigned bbase = (unsigned)__cvta_generic_to_shared(Bs);
    int arow = lane & 15;
    int brow = ((lane >> 4) << 3) + (lane & 7);
#pragma unroll
    for (int ks = 0; ks < BK; ks += 16) {
        unsigned a[4][4], b[2][4];
        int achunk = (ks >> 3) + (lane >> 4);
        int bchunk = (ks >> 3) + ((lane >> 3) & 1);
#pragma unroll
        for (int mi = 0; mi < 4; mi++)
            ldsm_x4(a[mi], abase + 2u * sw_off(wm + mi * 16 + arow, achunk));
#pragma unroll
        for (int nj2 = 0; nj2 < 2; nj2++)
            ldsm_x4(b[nj2], bbase + 2u * sw_off(wn + nj2 * 16 + brow, bchunk));
#pragma unroll
        for (int mi = 0; mi < 4; mi++)
#pragma unroll
            for (int nj = 0; nj < 4; nj++)
                mma_f16(acc[mi][nj], a[mi], &b[nj >> 1][(nj & 1) * 2]);
    }
}

// K2: hid = gelu(gather(x_h) @ W1T[e]^T + b1[e])
__global__ __launch_bounds__(256, 2) void k_ffn1(const float* __restrict__ b1) {
    int e   = blockIdx.z;
    int cnt = g_cnt[e];
    int m0  = blockIdx.y * 128;
    if (m0 >= cnt) return;
    int n0  = blockIdx.x * 128;

    __shared__ __align__(16) __half As[NSTG][128 * BK];
    __shared__ __align__(16) __half Bs[NSTG][128 * BK];
    __shared__ int toks[128];

    int tid = threadIdx.x;
    if (tid < 128) {
        int m = m0 + tid;
        toks[tid] = (m < cnt) ? g_tok[e * CAP + m] : -1;
    }
    __syncthreads();

    int lane = tid & 31, warp = tid >> 5;
    int gi = lane >> 2, qk = lane & 3;
    int wm = (warp >> 2) * 64, wn = (warp & 3) * 32;

    int lr = tid >> 1, c0 = (tid & 1) * 2;
    int my_tok = toks[lr];
    int abytes = (my_tok >= 0) ? 16 : 0;
    const __half* asrc = g_xh + (size_t)max(my_tok, 0) * EDIM;
    const __half* bsrc = g_w1t + ((size_t)e * HDIM + n0 + lr) * EDIM;
    unsigned so0 = sw_off(lr, c0), so1 = sw_off(lr, c0 + 1);

    float acc[4][4][4];
#pragma unroll
    for (int i = 0; i < 4; i++)
#pragma unroll
        for (int j = 0; j < 4; j++)
#pragma unroll
            for (int r = 0; r < 4; r++) acc[i][j][r] = 0.f;

    auto load_stage = [&](int buf, int k0) {
        cp16(As[buf] + so0, asrc + k0 + c0 * 8,       abytes);
        cp16(As[buf] + so1, asrc + k0 + c0 * 8 + 8,   abytes);
        cp16(Bs[buf] + so0, bsrc + k0 + c0 * 8,       16);
        cp16(Bs[buf] + so1, bsrc + k0 + c0 * 8 + 8,   16);
    };

    const int KT = EDIM / BK;       // 32
    load_stage(0, 0);      cp_commit();
    load_stage(1, BK);     cp_commit();
    for (int kt = 0; kt < KT; kt++) {
        if (kt + 2 < KT) load_stage((kt + 2) % NSTG, (kt + 2) * BK);
        cp_commit();                 // uniform group count (empty ok)
        cp_wait2();                  // stage kt resident; kt+1,kt+2 may pend
        __syncthreads();
        mma_stage(As[kt % NSTG], Bs[kt % NSTG], wm, wn, lane, acc);
    }

    // epilogue: +b1, exact GELU, store hid (fp16)
#pragma unroll
    for (int nj = 0; nj < 4; nj++) {
        int n = n0 + wn + nj * 8 + qk * 2;
        float b1a = b1[(size_t)e * HDIM + n];
        float b1b = b1[(size_t)e * HDIM + n + 1];
#pragma unroll
        for (int mi = 0; mi < 4; mi++) {
#pragma unroll
            for (int h = 0; h < 2; h++) {
                int m = m0 + wm + mi * 16 + gi + h * 8;
                if (m >= cnt) continue;
                float vx = gelu_exact(acc[mi][nj][h * 2 + 0] + b1a);
                float vy = gelu_exact(acc[mi][nj][h * 2 + 1] + b1b);
                *(half2*)(g_hid + ((size_t)e * CAP + m) * HDIM + n) =
                    __floats2half2_rn(vx, vy);
            }
        }
    }
}

// K3: out[tok] += w * (hid @ W2T[e]^T + b2[e])
__global__ __launch_bounds__(256, 2) void k_ffn2(const float* __restrict__ b2,
                                                 float* __restrict__ out) {
    int e   = blockIdx.z;
    int cnt = g_cnt[e];
    int m0  = blockIdx.y * 128;
    if (m0 >= cnt) return;
    int n0  = blockIdx.x * 128;

    __shared__ __align__(16) __half As[NSTG][128 * BK];
    __shared__ __align__(16) __half Bs[NSTG][128 * BK];
    __shared__ int   toks[128];
    __shared__ float wts[128];

    int tid = threadIdx.x;
    if (tid < 128) {
        int m = m0 + tid;
        bool v = (m < cnt);
        toks[tid] = v ? g_tok[e * CAP + m] : -1;
        wts[tid]  = v ? g_wgt[e * CAP + m] : 0.f;
    }
    __syncthreads();

    int mlim = cnt - m0;
    int lane = tid & 31, warp = tid >> 5;
    int gi = lane >> 2, qk = lane & 3;
    int wm = (warp >> 2) * 64, wn = (warp & 3) * 32;

    int lr = tid >> 1, c0 = (tid & 1) * 2;
    bool mval = (lr < mlim);
    int abytes = mval ? 16 : 0;
    const __half* asrc = g_hid + ((size_t)e * CAP + m0 + (mval ? lr : 0)) * HDIM;
    const __half* bsrc = g_w2t + ((size_t)e * EDIM + n0 + lr) * HDIM;
    unsigned so0 = sw_off(lr, c0), so1 = sw_off(lr, c0 + 1);

    float acc[4][4][4];
#pragma unroll
    for (int i = 0; i < 4; i++)
#pragma unroll
        for (int j = 0; j < 4; j++)
#pragma unroll
            for (int r = 0; r < 4; r++) acc[i][j][r] = 0.f;

    auto load_stage = [&](int buf, int k0) {
        cp16(As[buf] + so0, asrc + k0 + c0 * 8,       abytes);
        cp16(As[buf] + so1, asrc + k0 + c0 * 8 + 8,   abytes);
        cp16(Bs[buf] + so0, bsrc + k0 + c0 * 8,       16);
        cp16(Bs[buf] + so1, bsrc + k0 + c0 * 8 + 8,   16);
    };

    const int KT = HDIM / BK;       // 128
    load_stage(0, 0);      cp_commit();
    load_stage(1, BK);     cp_commit();
    for (int kt = 0; kt < KT; kt++) {
        if (kt + 2 < KT) load_stage((kt + 2) % NSTG, (kt + 2) * BK);
        cp_commit();
        cp_wait2();
        __syncthreads();
        mma_stage(As[kt % NSTG], Bs[kt % NSTG], wm, wn, lane, acc);
    }

#pragma unroll
    for (int nj = 0; nj < 4; nj++) {
        int n = n0 + wn + nj * 8 + qk * 2;
        float b2a = b2[(size_t)e * EDIM + n];
        float b2b = b2[(size_t)e * EDIM + n + 1];
#pragma unroll
        for (int mi = 0; mi < 4; mi++) {
#pragma unroll
            for (int h = 0; h < 2; h++) {
                int ml = wm + mi * 16 + gi + h * 8;
                int tok = toks[ml];
                if (tok < 0) continue;
                float w = wts[ml];
                float* op = out + (size_t)tok * EDIM + n;
                atomicAdd(op + 0, w * (acc[mi][nj][h * 2 + 0] + b2a));
                atomicAdd(op + 1, w * (acc[mi][nj][h * 2 + 1] + b2b));
            }
        }
    }
}

// ---------------------------------------------------------------------------
extern "C" void kernel_launch(void* const* d_in, const int* in_sizes, int n_in,
                              void* d_out, int out_size) {
    const float* x  = (const float*)d_in[0];
    const float* Wr = (const float*)d_in[1];
    const float* br = (const float*)d_in[2];
    const float* W1 = (const float*)d_in[3];
    const float* b1 = (const float*)d_in[4];
    const float* W2 = (const float*)d_in[5];
    const float* b2 = (const float*)d_in[6];
    float* out = (float*)d_out;
    (void)in_sizes; (void)n_in; (void)out_size;

    // Side streams + fork/join events (created once, outside any capture;
    // reused every call — same work graph every time).
    static cudaStream_t s1 = nullptr, s2 = nullptr;
    static cudaEvent_t ev_root = nullptr, ev_s1 = nullptr, ev_s2 = nullptr;
    if (s1 == nullptr) {
        cudaStreamCreateWithFlags(&s1, cudaStreamNonBlocking);
        cudaStreamCreateWithFlags(&s2, cudaStreamNonBlocking);
        cudaEventCreateWithFlags(&ev_root, cudaEventDisableTiming);
        cudaEventCreateWithFlags(&ev_s1, cudaEventDisableTiming);
        cudaEventCreateWithFlags(&ev_s2, cudaEventDisableTiming);
    }

    // main: counter init, then fork
    k_init<<<1, 32>>>();
    cudaEventRecord(ev_root, 0);
    cudaStreamWaitEvent(s1, ev_root, 0);
    cudaStreamWaitEvent(s2, ev_root, 0);

    // s1: zero out + W2 transpose (only needed by ffn2)
    k_zero<<<4096, 256, 0, s1>>>(out);
    {   dim3 g(EDIM / 32, HDIM / 64, NEXP);
        k_convW<1><<<g, 256, 0, s1>>>(W2); }
    cudaEventRecord(ev_s1, s1);

    // s2: router (needs x + g_cnt only)
    k_router<<<TNUM / 8, 256, 0, s2>>>(x, Wr, br);
    cudaEventRecord(ev_s2, s2);

    // main: x convert + W1 transpose (ffn1 critical path)
    k_convx<<<(TNUM * EDIM / 2 + 255) / 256, 256>>>(x);
    {   dim3 g(HDIM / 32, EDIM / 64, NEXP);
        k_convW<0><<<g, 256>>>(W1); }

    cudaStreamWaitEvent(0, ev_s2, 0);          // router done
    dim3 g1(HDIM / 128, CAP / 128, NEXP);
    k_ffn1<<<g1, 256>>>(b1);

    cudaStreamWaitEvent(0, ev_s1, 0);          // zero + W2T done
    dim3 g2(EDIM / 128, CAP / 128, NEXP);
    k_ffn2<<<g2, 256>>>(b2, out);
}